// round 2
// baseline (speedup 1.0000x reference)
#include <cuda_runtime.h>

// Problem constants
#define Bn 8
#define Nn 1024
#define Dn 512
#define Hn 8
#define DHn 64
#define BHn (Bn*Hn)          // 64
#define SCALE 0.125f         // 1/sqrt(64)

typedef unsigned long long ull;

__device__ __forceinline__ ull pk2(float lo, float hi) {
    ull r; asm("mov.b64 %0, {%1,%2};" : "=l"(r) : "f"(lo), "f"(hi)); return r;
}
__device__ __forceinline__ ull fma2(ull a, ull b, ull c) {
    ull d; asm("fma.rn.f32x2 %0, %1, %2, %3;" : "=l"(d) : "l"(a), "l"(b), "l"(c)); return d;
}
__device__ __forceinline__ float2 unpk(ull v) {
    float2 f; asm("mov.b64 {%0,%1}, %2;" : "=f"(f.x), "=f"(f.y) : "l"(v)); return f;
}

// Scratch (allocation-free rule: __device__ globals)
__device__ float g_q[(size_t)BHn*Nn*DHn];            // [bh, n, dh]
__device__ float g_k[(size_t)BHn*Nn*DHn];
__device__ float g_v[(size_t)BHn*Nn*DHn];
__device__ float g_attn[(size_t)BHn*Nn*Nn];          // 268 MB
__device__ float g_T[(size_t)BHn*Nn*2048];           // 512 MB, T[bh][i][l], l stride 2048
__device__ float g_otmp[(size_t)Bn*Nn*Dn];           // concat heads [b, n, h*dh]

// ---------------------------------------------------------------------------
// 128x128-tile NT GEMM, f32x2 packed: C[m,o] = sum_k A[m,k]*W[o,k]
// M=8192, Nout=512, K=512. MODE 0/1/2 -> g_q/g_k/g_v [bh,n,dh]; MODE 3 -> out+bias
// ---------------------------------------------------------------------------
template<int MODE>
__global__ __launch_bounds__(256) void gemm128(const float* __restrict__ A,
                                               const float* __restrict__ Wm,
                                               const float* __restrict__ bias,
                                               float* __restrict__ Cout)
{
    __shared__ float As[16][136];
    __shared__ float Bs[16][136];
    const int m0 = blockIdx.y * 128;
    const int n0 = blockIdx.x * 128;
    const int tid = threadIdx.x;
    const int tx = tid & 15, ty = tid >> 4;

    const float* Asrc = (MODE == 3) ? (const float*)g_otmp : A;

    ull acc[8][4];
#pragma unroll
    for (int i = 0; i < 8; i++)
#pragma unroll
        for (int p = 0; p < 4; p++) acc[i][p] = 0ULL;

    const int lrow = tid >> 1;          // 0..127
    const int lkk  = (tid & 1) * 8;     // 0,8

    for (int k0 = 0; k0 < Dn; k0 += 16) {
        float4 a0 = *(const float4*)(Asrc + (size_t)(m0 + lrow) * Dn + k0 + lkk);
        float4 a1 = *(const float4*)(Asrc + (size_t)(m0 + lrow) * Dn + k0 + lkk + 4);
        float4 b0 = *(const float4*)(Wm   + (size_t)(n0 + lrow) * Dn + k0 + lkk);
        float4 b1 = *(const float4*)(Wm   + (size_t)(n0 + lrow) * Dn + k0 + lkk + 4);
        As[lkk+0][lrow]=a0.x; As[lkk+1][lrow]=a0.y; As[lkk+2][lrow]=a0.z; As[lkk+3][lrow]=a0.w;
        As[lkk+4][lrow]=a1.x; As[lkk+5][lrow]=a1.y; As[lkk+6][lrow]=a1.z; As[lkk+7][lrow]=a1.w;
        Bs[lkk+0][lrow]=b0.x; Bs[lkk+1][lrow]=b0.y; Bs[lkk+2][lrow]=b0.z; Bs[lkk+3][lrow]=b0.w;
        Bs[lkk+4][lrow]=b1.x; Bs[lkk+5][lrow]=b1.y; Bs[lkk+6][lrow]=b1.z; Bs[lkk+7][lrow]=b1.w;
        __syncthreads();
#pragma unroll
        for (int k = 0; k < 16; k++) {
            float4 av0 = *(const float4*)&As[k][ty*4];
            float4 av1 = *(const float4*)&As[k][64 + ty*4];
            float4 bv0 = *(const float4*)&Bs[k][tx*4];
            float4 bv1 = *(const float4*)&Bs[k][64 + tx*4];
            ull pa[8], pb[4];
            pa[0]=pk2(av0.x,av0.x); pa[1]=pk2(av0.y,av0.y); pa[2]=pk2(av0.z,av0.z); pa[3]=pk2(av0.w,av0.w);
            pa[4]=pk2(av1.x,av1.x); pa[5]=pk2(av1.y,av1.y); pa[6]=pk2(av1.z,av1.z); pa[7]=pk2(av1.w,av1.w);
            pb[0]=pk2(bv0.x,bv0.y); pb[1]=pk2(bv0.z,bv0.w); pb[2]=pk2(bv1.x,bv1.y); pb[3]=pk2(bv1.z,bv1.w);
#pragma unroll
            for (int i = 0; i < 8; i++)
#pragma unroll
                for (int p = 0; p < 4; p++)
                    acc[i][p] = fma2(pa[i], pb[p], acc[i][p]);
        }
        __syncthreads();
    }

#pragma unroll
    for (int i = 0; i < 8; i++) {
        const int m = m0 + ((i < 4) ? (ty*4 + i) : (64 + ty*4 + i - 4));
#pragma unroll
        for (int p = 0; p < 4; p++) {
            const int o = n0 + ((p < 2) ? (tx*4 + p*2) : (64 + tx*4 + (p-2)*2));
            float2 v = unpk(acc[i][p]);
            if (MODE <= 2) {
                float* dst = (MODE == 0) ? g_q : (MODE == 1) ? g_k : g_v;
                const int bb = m >> 10, nn = m & (Nn - 1);
                const int hh = o >> 6,  dd = o & 63;
                *(float2*)&dst[(size_t)(((bb << 3) | hh) << 16) + (nn << 6) + dd] = v;
            } else {
                v.x += bias[o]; v.y += bias[o+1];
                *(float2*)&Cout[(size_t)m * Dn + o] = v;
            }
        }
    }
}

// ---------------------------------------------------------------------------
// Per-bh NT GEMM 128x128, K=64, f32x2 packed.
// REL=0: attn[bh,i,j] = Q_i . K_j            (raw, scale applied in softmax)
// REL=1: T[bh,i,l]    = Q_i . E[l]           (l clamped to 2046; stride 2048)
// ---------------------------------------------------------------------------
template<int REL>
__global__ __launch_bounds__(256) void qkt128(const float* __restrict__ E)
{
    __shared__ float As[16][136];
    __shared__ float Bs[16][136];
    const int bh = blockIdx.z;
    const int i0 = blockIdx.y * 128;
    const int j0 = blockIdx.x * 128;
    const int tid = threadIdx.x;
    const int tx = tid & 15, ty = tid >> 4;

    const float* qbase = g_q + (size_t)bh * Nn * DHn;
    const float* kbase = REL ? E : (g_k + (size_t)bh * Nn * DHn);

    ull acc[8][4];
#pragma unroll
    for (int i = 0; i < 8; i++)
#pragma unroll
        for (int p = 0; p < 4; p++) acc[i][p] = 0ULL;

    const int lrow = tid >> 1;
    const int lkk  = (tid & 1) * 8;

#pragma unroll
    for (int k0 = 0; k0 < DHn; k0 += 16) {
        int brow = j0 + lrow;
        if (REL) brow = (brow > 2046) ? 2046 : brow;
        float4 a0 = *(const float4*)(qbase + (size_t)(i0 + lrow) * DHn + k0 + lkk);
        float4 a1 = *(const float4*)(qbase + (size_t)(i0 + lrow) * DHn + k0 + lkk + 4);
        float4 b0 = *(const float4*)(kbase + (size_t)brow * DHn + k0 + lkk);
        float4 b1 = *(const float4*)(kbase + (size_t)brow * DHn + k0 + lkk + 4);
        As[lkk+0][lrow]=a0.x; As[lkk+1][lrow]=a0.y; As[lkk+2][lrow]=a0.z; As[lkk+3][lrow]=a0.w;
        As[lkk+4][lrow]=a1.x; As[lkk+5][lrow]=a1.y; As[lkk+6][lrow]=a1.z; As[lkk+7][lrow]=a1.w;
        Bs[lkk+0][lrow]=b0.x; Bs[lkk+1][lrow]=b0.y; Bs[lkk+2][lrow]=b0.z; Bs[lkk+3][lrow]=b0.w;
        Bs[lkk+4][lrow]=b1.x; Bs[lkk+5][lrow]=b1.y; Bs[lkk+6][lrow]=b1.z; Bs[lkk+7][lrow]=b1.w;
        __syncthreads();
#pragma unroll
        for (int k = 0; k < 16; k++) {
            float4 av0 = *(const float4*)&As[k][ty*4];
            float4 av1 = *(const float4*)&As[k][64 + ty*4];
            float4 bv0 = *(const float4*)&Bs[k][tx*4];
            float4 bv1 = *(const float4*)&Bs[k][64 + tx*4];
            ull pa[8], pb[4];
            pa[0]=pk2(av0.x,av0.x); pa[1]=pk2(av0.y,av0.y); pa[2]=pk2(av0.z,av0.z); pa[3]=pk2(av0.w,av0.w);
            pa[4]=pk2(av1.x,av1.x); pa[5]=pk2(av1.y,av1.y); pa[6]=pk2(av1.z,av1.z); pa[7]=pk2(av1.w,av1.w);
            pb[0]=pk2(bv0.x,bv0.y); pb[1]=pk2(bv0.z,bv0.w); pb[2]=pk2(bv1.x,bv1.y); pb[3]=pk2(bv1.z,bv1.w);
#pragma unroll
            for (int i = 0; i < 8; i++)
#pragma unroll
                for (int p = 0; p < 4; p++)
                    acc[i][p] = fma2(pa[i], pb[p], acc[i][p]);
        }
        __syncthreads();
    }

    const size_t ostride = REL ? 2048 : Nn;
    float* obase = REL ? (g_T + (size_t)bh * Nn * 2048)
                       : (g_attn + (size_t)bh * Nn * Nn);
#pragma unroll
    for (int i = 0; i < 8; i++) {
        const int ii = i0 + ((i < 4) ? (ty*4 + i) : (64 + ty*4 + i - 4));
#pragma unroll
        for (int p = 0; p < 4; p++) {
            const int jj = j0 + ((p < 2) ? (tx*4 + p*2) : (64 + tx*4 + (p-2)*2));
            float2 v = unpk(acc[i][p]);
            *(float2*)&obase[(size_t)ii * ostride + jj] = v;
        }
    }
}

// ---------------------------------------------------------------------------
// Row softmax with relative-bias gather:
//   v[j] = (QK[i,j] + T[i, j-i+1023]) * SCALE ; softmax over j; write attn.
// ---------------------------------------------------------------------------
__global__ __launch_bounds__(256) void softmax_rows()
{
    const size_t r = blockIdx.x;
    const int bh = (int)(r >> 10), i = (int)(r & 1023);
    float* p = g_attn + r * Nn;
    const float* t = g_T + ((size_t)bh * Nn + i) * 2048 + (1023 - i);
    const int tid = threadIdx.x;

    float v0 = (p[tid]       + t[tid])       * SCALE;
    float v1 = (p[tid + 256] + t[tid + 256]) * SCALE;
    float v2 = (p[tid + 512] + t[tid + 512]) * SCALE;
    float v3 = (p[tid + 768] + t[tid + 768]) * SCALE;

    float m = fmaxf(fmaxf(v0, v1), fmaxf(v2, v3));
#pragma unroll
    for (int o = 16; o; o >>= 1) m = fmaxf(m, __shfl_xor_sync(0xffffffffu, m, o));
    __shared__ float red[8];
    if ((tid & 31) == 0) red[tid >> 5] = m;
    __syncthreads();
    m = red[0];
#pragma unroll
    for (int w = 1; w < 8; w++) m = fmaxf(m, red[w]);

    v0 = __expf(v0 - m); v1 = __expf(v1 - m);
    v2 = __expf(v2 - m); v3 = __expf(v3 - m);
    float s = v0 + v1 + v2 + v3;
#pragma unroll
    for (int o = 16; o; o >>= 1) s += __shfl_xor_sync(0xffffffffu, s, o);
    __syncthreads();
    if ((tid & 31) == 0) red[tid >> 5] = s;
    __syncthreads();
    s = 0.f;
#pragma unroll
    for (int w = 0; w < 8; w++) s += red[w];

    const float inv = 1.0f / s;
    p[tid]       = v0 * inv;
    p[tid + 256] = v1 * inv;
    p[tid + 512] = v2 * inv;
    p[tid + 768] = v3 * inv;
}

// ---------------------------------------------------------------------------
// AV + phase: out[bh,i,d] = (sum_j P[i,j] V[j,d]) * phase[bh,i]
// Tile 256(i) x 64(d), K=1024, f32x2 packed. Writes concat-head g_otmp.
// ---------------------------------------------------------------------------
__global__ __launch_bounds__(256) void av_phase(const float* __restrict__ phase)
{
    __shared__ float Ps[16][264];   // [k][i], 256 + 8 pad
    __shared__ float Vs[16][72];    // [k][d]
    const int bh = blockIdx.y;
    const int i0 = blockIdx.x * 256;
    const int tid = threadIdx.x;
    const int tx = tid & 7, ty = tid >> 3;   // tx: 8 j-groups, ty: 32 i-groups

    const float* prow  = g_attn + ((size_t)bh * Nn + i0) * Nn;
    const float* vbase = g_v + (size_t)bh * Nn * DHn;

    ull acc[8][4];
#pragma unroll
    for (int i = 0; i < 8; i++)
#pragma unroll
        for (int p = 0; p < 4; p++) acc[i][p] = 0ULL;

    const int vr = tid >> 4;            // 0..15 (k row)
    const int vd = (tid & 15) * 4;      // 0..60

    for (int k0 = 0; k0 < Nn; k0 += 16) {
        // load P chunk: 256 rows x 16 k
#pragma unroll
        for (int u = 0; u < 4; u++) {
            const int idx = tid + u * 256;
            const int pr = idx >> 2, pkk = (idx & 3) * 4;
            float4 vp = *(const float4*)(prow + (size_t)pr * Nn + k0 + pkk);
            Ps[pkk+0][pr] = vp.x; Ps[pkk+1][pr] = vp.y;
            Ps[pkk+2][pr] = vp.z; Ps[pkk+3][pr] = vp.w;
        }
        // load V chunk: 16 rows x 64 d (no transpose)
        {
            float4 vv = *(const float4*)(vbase + (size_t)(k0 + vr) * DHn + vd);
            *(float4*)&Vs[vr][vd] = vv;
        }
        __syncthreads();
#pragma unroll
        for (int k = 0; k < 16; k++) {
            float4 av0 = *(const float4*)&Ps[k][ty*4];
            float4 av1 = *(const float4*)&Ps[k][128 + ty*4];
            float4 bv0 = *(const float4*)&Vs[k][tx*4];
            float4 bv1 = *(const float4*)&Vs[k][32 + tx*4];
            ull pa[8], pb[4];
            pa[0]=pk2(av0.x,av0.x); pa[1]=pk2(av0.y,av0.y); pa[2]=pk2(av0.z,av0.z); pa[3]=pk2(av0.w,av0.w);
            pa[4]=pk2(av1.x,av1.x); pa[5]=pk2(av1.y,av1.y); pa[6]=pk2(av1.z,av1.z); pa[7]=pk2(av1.w,av1.w);
            pb[0]=pk2(bv0.x,bv0.y); pb[1]=pk2(bv0.z,bv0.w); pb[2]=pk2(bv1.x,bv1.y); pb[3]=pk2(bv1.z,bv1.w);
#pragma unroll
            for (int i = 0; i < 8; i++)
#pragma unroll
                for (int p = 0; p < 4; p++)
                    acc[i][p] = fma2(pa[i], pb[p], acc[i][p]);
        }
        __syncthreads();
    }

    const int bb = bh >> 3, hh = bh & 7;
#pragma unroll
    for (int i = 0; i < 8; i++) {
        const int gi = i0 + ((i < 4) ? (ty*4 + i) : (128 + ty*4 + i - 4));
        const float ph = phase[(size_t)bh * Nn + gi];
#pragma unroll
        for (int p = 0; p < 4; p++) {
            const int dd = (p < 2) ? (tx*4 + p*2) : (32 + tx*4 + (p-2)*2);
            float2 v = unpk(acc[i][p]);
            v.x *= ph; v.y *= ph;
            *(float2*)&g_otmp[(size_t)(bb * Nn + gi) * Dn + hh*64 + dd] = v;
        }
    }
}

// ---------------------------------------------------------------------------
extern "C" void kernel_launch(void* const* d_in, const int* in_sizes, int n_in,
                              void* d_out, int out_size)
{
    const float* x     = (const float*)d_in[0];
    const float* phase = (const float*)d_in[1];
    const float* E     = (const float*)d_in[2];
    const float* Wq    = (const float*)d_in[3];
    const float* Wk    = (const float*)d_in[4];
    const float* Wv    = (const float*)d_in[5];
    const float* Wo    = (const float*)d_in[6];
    const float* bo    = (const float*)d_in[7];
    float* out = (float*)d_out;

    dim3 gproj(Dn / 128, (Bn * Nn) / 128);   // (4, 64)

    gemm128<0><<<gproj, 256>>>(x, Wq, nullptr, nullptr);
    gemm128<1><<<gproj, 256>>>(x, Wk, nullptr, nullptr);
    gemm128<2><<<gproj, 256>>>(x, Wv, nullptr, nullptr);

    qkt128<0><<<dim3(Nn / 128, Nn / 128, BHn), 256>>>(nullptr);   // QK
    qkt128<1><<<dim3(16, Nn / 128, BHn), 256>>>(E);               // T = Q @ E^T

    softmax_rows<<<BHn * Nn, 256>>>();

    av_phase<<<dim3(Nn / 256, BHn), 256>>>(phase);

    gemm128<3><<<gproj, 256>>>(nullptr, Wo, bo, out);
}

// round 4
// speedup vs baseline: 1.3539x; 1.3539x over previous
#include <cuda_runtime.h>

// Problem constants
#define Bn 8
#define Nn 1024
#define Dn 512
#define Hn 8
#define DHn 64
#define BHn (Bn*Hn)          // 64
#define SCALE 0.125f         // 1/sqrt(64)

typedef unsigned long long ull;

__device__ __forceinline__ ull pk2(float lo, float hi) {
    ull r; asm("mov.b64 %0, {%1,%2};" : "=l"(r) : "f"(lo), "f"(hi)); return r;
}
__device__ __forceinline__ ull fma2(ull a, ull b, ull c) {
    ull d; asm("fma.rn.f32x2 %0, %1, %2, %3;" : "=l"(d) : "l"(a), "l"(b), "l"(c)); return d;
}
__device__ __forceinline__ float2 unpk(ull v) {
    float2 f; asm("mov.b64 {%0,%1}, %2;" : "=f"(f.x), "=f"(f.y) : "l"(v)); return f;
}

// Scratch (allocation-free rule: __device__ globals)
__device__ float g_q[(size_t)BHn*Nn*DHn];            // [bh, n, dh]
__device__ float g_k[(size_t)BHn*Nn*DHn];
__device__ float g_v[(size_t)BHn*Nn*DHn];
__device__ float g_otmp[(size_t)Bn*Nn*Dn];           // concat heads [b, n, h*dh]

// ---------------------------------------------------------------------------
// 128x128-tile NT GEMM, f32x2 packed: C[m,o] = sum_k A[m,k]*W[o,k]
// M=8192, Nout=512, K=512. MODE 0/1/2 -> g_q/g_k/g_v [bh,n,dh]; MODE 3 -> out+bias
// ---------------------------------------------------------------------------
template<int MODE>
__global__ __launch_bounds__(256) void gemm128(const float* __restrict__ A,
                                               const float* __restrict__ Wm,
                                               const float* __restrict__ bias,
                                               float* __restrict__ Cout)
{
    __shared__ float As[16][136];
    __shared__ float Bs[16][136];
    const int m0 = blockIdx.y * 128;
    const int n0 = blockIdx.x * 128;
    const int tid = threadIdx.x;
    const int tx = tid & 15, ty = tid >> 4;

    const float* Asrc = (MODE == 3) ? (const float*)g_otmp : A;

    ull acc[8][4];
#pragma unroll
    for (int i = 0; i < 8; i++)
#pragma unroll
        for (int p = 0; p < 4; p++) acc[i][p] = 0ULL;

    const int lrow = tid >> 1;          // 0..127
    const int lkk  = (tid & 1) * 8;     // 0,8

    for (int k0 = 0; k0 < Dn; k0 += 16) {
        float4 a0 = *(const float4*)(Asrc + (size_t)(m0 + lrow) * Dn + k0 + lkk);
        float4 a1 = *(const float4*)(Asrc + (size_t)(m0 + lrow) * Dn + k0 + lkk + 4);
        float4 b0 = *(const float4*)(Wm   + (size_t)(n0 + lrow) * Dn + k0 + lkk);
        float4 b1 = *(const float4*)(Wm   + (size_t)(n0 + lrow) * Dn + k0 + lkk + 4);
        As[lkk+0][lrow]=a0.x; As[lkk+1][lrow]=a0.y; As[lkk+2][lrow]=a0.z; As[lkk+3][lrow]=a0.w;
        As[lkk+4][lrow]=a1.x; As[lkk+5][lrow]=a1.y; As[lkk+6][lrow]=a1.z; As[lkk+7][lrow]=a1.w;
        Bs[lkk+0][lrow]=b0.x; Bs[lkk+1][lrow]=b0.y; Bs[lkk+2][lrow]=b0.z; Bs[lkk+3][lrow]=b0.w;
        Bs[lkk+4][lrow]=b1.x; Bs[lkk+5][lrow]=b1.y; Bs[lkk+6][lrow]=b1.z; Bs[lkk+7][lrow]=b1.w;
        __syncthreads();
#pragma unroll
        for (int k = 0; k < 16; k++) {
            float4 av0 = *(const float4*)&As[k][ty*4];
            float4 av1 = *(const float4*)&As[k][64 + ty*4];
            float4 bv0 = *(const float4*)&Bs[k][tx*4];
            float4 bv1 = *(const float4*)&Bs[k][64 + tx*4];
            ull pa[8], pb[4];
            pa[0]=pk2(av0.x,av0.x); pa[1]=pk2(av0.y,av0.y); pa[2]=pk2(av0.z,av0.z); pa[3]=pk2(av0.w,av0.w);
            pa[4]=pk2(av1.x,av1.x); pa[5]=pk2(av1.y,av1.y); pa[6]=pk2(av1.z,av1.z); pa[7]=pk2(av1.w,av1.w);
            pb[0]=pk2(bv0.x,bv0.y); pb[1]=pk2(bv0.z,bv0.w); pb[2]=pk2(bv1.x,bv1.y); pb[3]=pk2(bv1.z,bv1.w);
#pragma unroll
            for (int i = 0; i < 8; i++)
#pragma unroll
                for (int p = 0; p < 4; p++)
                    acc[i][p] = fma2(pa[i], pb[p], acc[i][p]);
        }
        __syncthreads();
    }

#pragma unroll
    for (int i = 0; i < 8; i++) {
        const int m = m0 + ((i < 4) ? (ty*4 + i) : (64 + ty*4 + i - 4));
#pragma unroll
        for (int p = 0; p < 4; p++) {
            const int o = n0 + ((p < 2) ? (tx*4 + p*2) : (64 + tx*4 + (p-2)*2));
            float2 v = unpk(acc[i][p]);
            if (MODE <= 2) {
                float* dst = (MODE == 0) ? g_q : (MODE == 1) ? g_k : g_v;
                const int bb = m >> 10, nn = m & (Nn - 1);
                const int hh = o >> 6,  dd = o & 63;
                *(float2*)&dst[(size_t)(((bb << 3) | hh) << 16) + (nn << 6) + dd] = v;
            } else {
                v.x += bias[o]; v.y += bias[o+1];
                *(float2*)&Cout[(size_t)m * Dn + o] = v;
            }
        }
    }
}

// ---------------------------------------------------------------------------
// Fused flash attention with Music-Transformer relative bias + phase.
// One block = (bh, 64-row i-tile). 256 threads. j-tiles of 128.
//   S[i,j] = (Q_i.K_j + Q_i.E[j-i+1023]) * SCALE
//   online softmax; O = P @ V; out = O * phase / rowsum
// Bias per j-tile: Bt[64x191] = Q_tile @ E_window^T  (window always in-bounds)
// ---------------------------------------------------------------------------
#define QS_STRIDE 68
#define KS_STRIDE 136
#define VS_STRIDE 68
#define BT_STRIDE 194
#define ES_STRIDE 192
#define PS_STRIDE 68
#define SM_QS 0
#define SM_KS (SM_QS + 64*QS_STRIDE)
#define SM_VS (SM_KS + 64*KS_STRIDE)
#define SM_BT (SM_VS + 128*VS_STRIDE)
#define SM_ES (SM_BT + 64*BT_STRIDE)
#define SM_FLOATS (SM_ES + 64*ES_STRIDE)
#define SMEM_BYTES (SM_FLOATS * 4)

__global__ __launch_bounds__(256, 1) void flash_attn(const float* __restrict__ E,
                                                     const float* __restrict__ phase)
{
    extern __shared__ float sm[];
    float* Qs = sm + SM_QS;       // [64][68]  d-major: Qs[d*68 + i]
    float* Ks = sm + SM_KS;       // [64][136] d-major: Ks[d*136 + j]
    float* Vs = sm + SM_VS;       // [128][68] j-major: Vs[j*68 + d]
    float* Bt = sm + SM_BT;       // [64][194] Bt[i*194 + r]
    float* Es = sm + SM_ES;       // [64][192] d-major: Es[d*192 + r]
    float* Ps = sm + SM_ES;       // [128][68] union with Es: Ps[j*68 + i]

    const int bh = blockIdx.y;
    const int i0 = blockIdx.x * 64;
    const int tid = threadIdx.x;
    const int tx = tid & 15, ty = tid >> 4;
    const int ib = ty * 4;        // 4 i-rows per thread
    const int jb = tx * 8;        // 8 j-cols (S phase)
    const int db = tx * 4;        // 4 d-cols (O phase)
    const int rb = tx * 12;       // 12 r-cols (Bt phase)

    const float* qg = g_q + ((size_t)bh * Nn + i0) * DHn;
    const float* kg = g_k + (size_t)bh * Nn * DHn;
    const float* vg = g_v + (size_t)bh * Nn * DHn;

    // Load Q tile (transpose to d-major), resident whole kernel
#pragma unroll
    for (int u = 0; u < 4; u++) {
        const int f4 = tid + u * 256;          // 0..1023
        const int row = f4 >> 4, c4 = (f4 & 15) * 4;
        float4 v = *(const float4*)(qg + row * DHn + c4);
        Qs[(c4+0)*QS_STRIDE + row] = v.x; Qs[(c4+1)*QS_STRIDE + row] = v.y;
        Qs[(c4+2)*QS_STRIDE + row] = v.z; Qs[(c4+3)*QS_STRIDE + row] = v.w;
    }

    ull o_acc[4][2];
    float m_i[4], l_i[4];
#pragma unroll
    for (int i = 0; i < 4; i++) {
        m_i[i] = -1e30f; l_i[i] = 0.f;
        o_acc[i][0] = 0ULL; o_acc[i][1] = 0ULL;
    }

    for (int j0 = 0; j0 < Nn; j0 += 128) {
        __syncthreads();   // prev AV done before overwriting Ks/Vs/Es(Ps)

        // K tile 128x64 -> d-major
#pragma unroll
        for (int u = 0; u < 8; u++) {
            const int f4 = tid + u * 256;      // 0..2047
            const int row = f4 >> 4, c4 = (f4 & 15) * 4;
            float4 v = *(const float4*)(kg + (size_t)(j0 + row) * DHn + c4);
            Ks[(c4+0)*KS_STRIDE + row] = v.x; Ks[(c4+1)*KS_STRIDE + row] = v.y;
            Ks[(c4+2)*KS_STRIDE + row] = v.z; Ks[(c4+3)*KS_STRIDE + row] = v.w;
        }
        // V tile 128x64 natural
#pragma unroll
        for (int u = 0; u < 8; u++) {
            const int f4 = tid + u * 256;
            const int row = f4 >> 4, c4 = (f4 & 15) * 4;
            *(float4*)(Vs + row * VS_STRIDE + c4) =
                *(const float4*)(vg + (size_t)(j0 + row) * DHn + c4);
        }
        // E window: 191 rows starting at l0 (always within [0,2046]) -> d-major
        const int l0 = j0 - i0 + 960;
#pragma unroll
        for (int u = 0; u < 12; u++) {
            const int f4 = tid + u * 256;      // need < 191*16 = 3056
            if (f4 < 191 * 16) {
                const int r = f4 >> 4, c4 = (f4 & 15) * 4;
                float4 v = *(const float4*)(E + (size_t)(l0 + r) * DHn + c4);
                Es[(c4+0)*ES_STRIDE + r] = v.x; Es[(c4+1)*ES_STRIDE + r] = v.y;
                Es[(c4+2)*ES_STRIDE + r] = v.z; Es[(c4+3)*ES_STRIDE + r] = v.w;
            }
        }
        __syncthreads();

        // ---- Bt = Q_tile @ E_window^T  (64 x 191, col 191 unused) ----
        {
            ull bt[4][6];
#pragma unroll
            for (int i = 0; i < 4; i++)
#pragma unroll
                for (int p = 0; p < 6; p++) bt[i][p] = 0ULL;
#pragma unroll 8
            for (int d = 0; d < 64; d++) {
                float4 a = *(const float4*)(Qs + d * QS_STRIDE + ib);
                ulonglong2 e0 = *(const ulonglong2*)(Es + d * ES_STRIDE + rb);
                ulonglong2 e1 = *(const ulonglong2*)(Es + d * ES_STRIDE + rb + 4);
                ulonglong2 e2 = *(const ulonglong2*)(Es + d * ES_STRIDE + rb + 8);
                ull pa[4] = { pk2(a.x,a.x), pk2(a.y,a.y), pk2(a.z,a.z), pk2(a.w,a.w) };
                ull pb[6] = { e0.x, e0.y, e1.x, e1.y, e2.x, e2.y };
#pragma unroll
                for (int i = 0; i < 4; i++)
#pragma unroll
                    for (int p = 0; p < 6; p++)
                        bt[i][p] = fma2(pa[i], pb[p], bt[i][p]);
            }
#pragma unroll
            for (int i = 0; i < 4; i++)
#pragma unroll
                for (int p = 0; p < 6; p++)
                    *(float2*)(Bt + (ib + i) * BT_STRIDE + rb + p * 2) = unpk(bt[i][p]);
        }
        __syncthreads();

        // ---- S = Q K^T + bias, scaled ----
        float s[4][8];
        {
            ull sa[4][4];
#pragma unroll
            for (int i = 0; i < 4; i++)
#pragma unroll
                for (int p = 0; p < 4; p++) sa[i][p] = 0ULL;
#pragma unroll 8
            for (int d = 0; d < 64; d++) {
                float4 a = *(const float4*)(Qs + d * QS_STRIDE + ib);
                ulonglong2 k0 = *(const ulonglong2*)(Ks + d * KS_STRIDE + jb);
                ulonglong2 k1 = *(const ulonglong2*)(Ks + d * KS_STRIDE + jb + 4);
                ull pa[4] = { pk2(a.x,a.x), pk2(a.y,a.y), pk2(a.z,a.z), pk2(a.w,a.w) };
                ull pb[4] = { k0.x, k0.y, k1.x, k1.y };
#pragma unroll
                for (int i = 0; i < 4; i++)
#pragma unroll
                    for (int p = 0; p < 4; p++)
                        sa[i][p] = fma2(pa[i], pb[p], sa[i][p]);
            }
#pragma unroll
            for (int i = 0; i < 4; i++)
#pragma unroll
                for (int p = 0; p < 4; p++) {
                    float2 v = unpk(sa[i][p]);
                    s[i][2*p] = v.x; s[i][2*p+1] = v.y;
                }
#pragma unroll
            for (int i = 0; i < 4; i++) {
                const int row = ib + i;
#pragma unroll
                for (int j = 0; j < 8; j++) {
                    const int col = jb + j - row + 63;      // in [0,190]
                    s[i][j] = (s[i][j] + Bt[row * BT_STRIDE + col]) * SCALE;
                }
            }
        }

        // ---- online softmax (row groups of 16 tx lanes share same i-rows) ----
#pragma unroll
        for (int i = 0; i < 4; i++) {
            float mx = s[i][0];
#pragma unroll
            for (int j = 1; j < 8; j++) mx = fmaxf(mx, s[i][j]);
#pragma unroll
            for (int o = 8; o; o >>= 1)
                mx = fmaxf(mx, __shfl_xor_sync(0xffffffffu, mx, o));
            const float mn = fmaxf(m_i[i], mx);
            const float al = __expf(m_i[i] - mn);
            m_i[i] = mn;
            float sum = 0.f;
#pragma unroll
            for (int j = 0; j < 8; j++) {
                s[i][j] = __expf(s[i][j] - mn);
                sum += s[i][j];
            }
#pragma unroll
            for (int o = 8; o; o >>= 1)
                sum += __shfl_xor_sync(0xffffffffu, sum, o);
            l_i[i] = l_i[i] * al + sum;
            const ull aa = pk2(al, al);
            o_acc[i][0] = fma2(aa, o_acc[i][0], 0ULL);
            o_acc[i][1] = fma2(aa, o_acc[i][1], 0ULL);
        }

        // write P (transposed, j-major) — float4 across the 4 i-rows
#pragma unroll
        for (int j = 0; j < 8; j++) {
            float4 v = make_float4(s[0][j], s[1][j], s[2][j], s[3][j]);
            *(float4*)(Ps + (jb + j) * PS_STRIDE + ib) = v;
        }
        __syncthreads();

        // ---- O += P @ V ----
#pragma unroll 8
        for (int k = 0; k < 128; k++) {
            float4 a = *(const float4*)(Ps + k * PS_STRIDE + ib);
            ulonglong2 b = *(const ulonglong2*)(Vs + k * VS_STRIDE + db);
            ull pa[4] = { pk2(a.x,a.x), pk2(a.y,a.y), pk2(a.z,a.z), pk2(a.w,a.w) };
#pragma unroll
            for (int i = 0; i < 4; i++) {
                o_acc[i][0] = fma2(pa[i], b.x, o_acc[i][0]);
                o_acc[i][1] = fma2(pa[i], b.y, o_acc[i][1]);
            }
        }
    }

    // ---- epilogue: out = O * phase / rowsum -> concat-head g_otmp ----
    const int bb = bh >> 3, hh = bh & 7;
#pragma unroll
    for (int i = 0; i < 4; i++) {
        const int gi = i0 + ib + i;
        const float f = phase[(size_t)bh * Nn + gi] / l_i[i];
#pragma unroll
        for (int p = 0; p < 2; p++) {
            float2 v = unpk(o_acc[i][p]);
            v.x *= f; v.y *= f;
            *(float2*)&g_otmp[(size_t)(bb * Nn + gi) * Dn + hh * 64 + db + p * 2] = v;
        }
    }
}

// ---------------------------------------------------------------------------
extern "C" void kernel_launch(void* const* d_in, const int* in_sizes, int n_in,
                              void* d_out, int out_size)
{
    const float* x     = (const float*)d_in[0];
    const float* phase = (const float*)d_in[1];
    const float* E     = (const float*)d_in[2];
    const float* Wq    = (const float*)d_in[3];
    const float* Wk    = (const float*)d_in[4];
    const float* Wv    = (const float*)d_in[5];
    const float* Wo    = (const float*)d_in[6];
    const float* bo    = (const float*)d_in[7];
    float* out = (float*)d_out;

    // One-time attribute set (first call is the non-captured correctness run)
    static const bool s_init = []() {
        cudaFuncSetAttribute(flash_attn, cudaFuncAttributeMaxDynamicSharedMemorySize,
                             SMEM_BYTES);
        return true;
    }();
    (void)s_init;

    dim3 gproj(Dn / 128, (Bn * Nn) / 128);   // (4, 64)

    gemm128<0><<<gproj, 256>>>(x, Wq, nullptr, nullptr);
    gemm128<1><<<gproj, 256>>>(x, Wk, nullptr, nullptr);
    gemm128<2><<<gproj, 256>>>(x, Wv, nullptr, nullptr);

    flash_attn<<<dim3(Nn / 64, BHn), 256, SMEM_BYTES>>>(E, phase);

    gemm128<3><<<gproj, 256>>>(nullptr, Wo, bo, out);
}

// round 6
// speedup vs baseline: 1.8316x; 1.3528x over previous
#include <cuda_runtime.h>

// Problem constants
#define Bn 8
#define Nn 1024
#define Dn 512
#define Hn 8
#define DHn 64
#define BHn (Bn*Hn)          // 64
#define SCALE 0.125f         // 1/sqrt(64)

typedef unsigned long long ull;

__device__ __forceinline__ ull pk2(float lo, float hi) {
    ull r; asm("mov.b64 %0, {%1,%2};" : "=l"(r) : "f"(lo), "f"(hi)); return r;
}
__device__ __forceinline__ ull fma2(ull a, ull b, ull c) {
    ull d; asm("fma.rn.f32x2 %0, %1, %2, %3;" : "=l"(d) : "l"(a), "l"(b), "l"(c)); return d;
}
__device__ __forceinline__ ull add2(ull a, ull b) {
    ull d; asm("add.rn.f32x2 %0, %1, %2;" : "=l"(d) : "l"(a), "l"(b)); return d;
}
__device__ __forceinline__ float2 unpk(ull v) {
    float2 f; asm("mov.b64 {%0,%1}, %2;" : "=f"(f.x), "=f"(f.y) : "l"(v)); return f;
}

// Scratch (allocation-free rule: __device__ globals)
__device__ float g_q[(size_t)BHn*Nn*DHn];            // [bh, n, dh]
__device__ float g_k[(size_t)BHn*Nn*DHn];
__device__ float g_v[(size_t)BHn*Nn*DHn];
__device__ float g_otmp[(size_t)Bn*Nn*Dn];           // concat heads [b, n, h*dh]

// ---------------------------------------------------------------------------
// 128x128-tile NT GEMM, f32x2 packed: C[m,o] = sum_k A[m,k]*W[o,k]
// ---------------------------------------------------------------------------
template<int MODE>
__global__ __launch_bounds__(256) void gemm128(const float* __restrict__ A,
                                               const float* __restrict__ Wm,
                                               const float* __restrict__ bias,
                                               float* __restrict__ Cout)
{
    __shared__ float As[16][136];
    __shared__ float Bs[16][136];
    const int m0 = blockIdx.y * 128;
    const int n0 = blockIdx.x * 128;
    const int tid = threadIdx.x;
    const int tx = tid & 15, ty = tid >> 4;

    const float* Asrc = (MODE == 3) ? (const float*)g_otmp : A;

    ull acc[8][4];
#pragma unroll
    for (int i = 0; i < 8; i++)
#pragma unroll
        for (int p = 0; p < 4; p++) acc[i][p] = 0ULL;

    const int lrow = tid >> 1;          // 0..127
    const int lkk  = (tid & 1) * 8;     // 0,8

    for (int k0 = 0; k0 < Dn; k0 += 16) {
        float4 a0 = *(const float4*)(Asrc + (size_t)(m0 + lrow) * Dn + k0 + lkk);
        float4 a1 = *(const float4*)(Asrc + (size_t)(m0 + lrow) * Dn + k0 + lkk + 4);
        float4 b0 = *(const float4*)(Wm   + (size_t)(n0 + lrow) * Dn + k0 + lkk);
        float4 b1 = *(const float4*)(Wm   + (size_t)(n0 + lrow) * Dn + k0 + lkk + 4);
        As[lkk+0][lrow]=a0.x; As[lkk+1][lrow]=a0.y; As[lkk+2][lrow]=a0.z; As[lkk+3][lrow]=a0.w;
        As[lkk+4][lrow]=a1.x; As[lkk+5][lrow]=a1.y; As[lkk+6][lrow]=a1.z; As[lkk+7][lrow]=a1.w;
        Bs[lkk+0][lrow]=b0.x; Bs[lkk+1][lrow]=b0.y; Bs[lkk+2][lrow]=b0.z; Bs[lkk+3][lrow]=b0.w;
        Bs[lkk+4][lrow]=b1.x; Bs[lkk+5][lrow]=b1.y; Bs[lkk+6][lrow]=b1.z; Bs[lkk+7][lrow]=b1.w;
        __syncthreads();
#pragma unroll
        for (int k = 0; k < 16; k++) {
            float4 av0 = *(const float4*)&As[k][ty*4];
            float4 av1 = *(const float4*)&As[k][64 + ty*4];
            float4 bv0 = *(const float4*)&Bs[k][tx*4];
            float4 bv1 = *(const float4*)&Bs[k][64 + tx*4];
            ull pa[8], pb[4];
            pa[0]=pk2(av0.x,av0.x); pa[1]=pk2(av0.y,av0.y); pa[2]=pk2(av0.z,av0.z); pa[3]=pk2(av0.w,av0.w);
            pa[4]=pk2(av1.x,av1.x); pa[5]=pk2(av1.y,av1.y); pa[6]=pk2(av1.z,av1.z); pa[7]=pk2(av1.w,av1.w);
            pb[0]=pk2(bv0.x,bv0.y); pb[1]=pk2(bv0.z,bv0.w); pb[2]=pk2(bv1.x,bv1.y); pb[3]=pk2(bv1.z,bv1.w);
#pragma unroll
            for (int i = 0; i < 8; i++)
#pragma unroll
                for (int p = 0; p < 4; p++)
                    acc[i][p] = fma2(pa[i], pb[p], acc[i][p]);
        }
        __syncthreads();
    }

#pragma unroll
    for (int i = 0; i < 8; i++) {
        const int m = m0 + ((i < 4) ? (ty*4 + i) : (64 + ty*4 + i - 4));
#pragma unroll
        for (int p = 0; p < 4; p++) {
            const int o = n0 + ((p < 2) ? (tx*4 + p*2) : (64 + tx*4 + (p-2)*2));
            float2 v = unpk(acc[i][p]);
            if (MODE <= 2) {
                float* dst = (MODE == 0) ? g_q : (MODE == 1) ? g_k : g_v;
                const int bb = m >> 10, nn = m & (Nn - 1);
                const int hh = o >> 6,  dd = o & 63;
                *(float2*)&dst[(size_t)(((bb << 3) | hh) << 16) + (nn << 6) + dd] = v;
            } else {
                v.x += bias[o]; v.y += bias[o+1];
                *(float2*)&Cout[(size_t)m * Dn + o] = v;
            }
        }
    }
}

// ---------------------------------------------------------------------------
// Fused flash attention, tile 64i x 256j, 256 threads, micro 8i x 8j.
//   S[i,j] = sum_d Q[d,i] * (K[d,j] + E[d, j-i+63(rel)])   -- combined operand
//   online softmax; O = P @ V (2-way k-split, merged at end); out *= phase/l
// ---------------------------------------------------------------------------
#define JT 256
#define WIN 319
#define QS_ST 68
#define KS_ST 260
#define VS_ST 64
#define ES_ST 320
#define PS_ST 260
#define SM_KS_OFF (64*QS_ST)                 // 4352
#define SM_VS_OFF (SM_KS_OFF + 64*KS_ST)     // 20992
#define SM_EP_OFF (SM_VS_OFF + JT*VS_ST)     // 37376
#define SM_TOT    (SM_EP_OFF + 64*ES_ST)     // 57856 floats
#define SMEM_BYTES (SM_TOT * 4)              // 231424 B

__global__ __launch_bounds__(256, 1) void flash_attn(const float* __restrict__ Eg,
                                                     const float* __restrict__ phase)
{
    extern __shared__ float sm[];
    float* Qs = sm;                    // [64 d][QS_ST]: Qs[d*68 + i]
    float* Ks = sm + SM_KS_OFF;        // [64 d][KS_ST]: Ks[d*260 + j]
    float* Vs = sm + SM_VS_OFF;        // [256 k][64 d]
    float* Es = sm + SM_EP_OFF;        // [64 d][ES_ST]: Es[d*320 + r]
    float* Ps = sm + SM_EP_OFF;        // union: [64 i][PS_ST]
    float* Om = sm + SM_EP_OFF;        // union: [2][64][64] merge buffer

    const int bh = blockIdx.y;
    const int i0 = blockIdx.x * 64;
    const int tid = threadIdx.x;
    const int tx = tid & 31;           // 32 j-groups of 8
    const int ty = tid >> 5;           // 8 i-groups of 8
    const int ib = ty * 8;
    const int jb = tx * 8;
    const int wb = jb - ib + 56;       // E window base, in [0,304], mult of 4
    const int lane = tid & 31;
    const int grp  = tid >> 5;         // c-group for loads (8 groups)
    const int tk = (tid >> 4) & 1;     // AV k-half
    const int dq = (tid & 15) * 4;     // AV d-cols

    const float* qg = g_q + ((size_t)bh * Nn + i0) * DHn;
    const float* kg = g_k + (size_t)bh * Nn * DHn;
    const float* vg = g_v + (size_t)bh * Nn * DHn;

    // ---- load Q tile 64x64 -> d-major (conflict-free: lane == row) ----
#pragma unroll
    for (int u = 0; u < 4; u++) {
        const int r  = lane + (u & 1) * 32;
        const int c4 = grp * 4 + (u >> 1) * 32;
        float4 v = *(const float4*)(qg + r * DHn + c4);
        Qs[(c4+0)*QS_ST + r] = v.x; Qs[(c4+1)*QS_ST + r] = v.y;
        Qs[(c4+2)*QS_ST + r] = v.z; Qs[(c4+3)*QS_ST + r] = v.w;
    }

    ull o_acc[8][2];
    float m_i[8], l_i[8];
#pragma unroll
    for (int i = 0; i < 8; i++) {
        m_i[i] = -1e30f; l_i[i] = 0.f;
        o_acc[i][0] = 0ULL; o_acc[i][1] = 0ULL;
    }

    for (int j0 = 0; j0 < Nn; j0 += JT) {
        __syncthreads();   // prev tile AV done: Ks/Vs/Es(Ps) reusable

        // K tile 256x64 -> d-major
#pragma unroll
        for (int u = 0; u < 16; u++) {
            const int j  = lane + (u & 7) * 32;
            const int c4 = grp * 4 + (u >> 3) * 32;
            float4 v = *(const float4*)(kg + (size_t)(j0 + j) * DHn + c4);
            Ks[(c4+0)*KS_ST + j] = v.x; Ks[(c4+1)*KS_ST + j] = v.y;
            Ks[(c4+2)*KS_ST + j] = v.z; Ks[(c4+3)*KS_ST + j] = v.w;
        }
        // V tile 256x64 natural (coalesced)
#pragma unroll
        for (int u = 0; u < 16; u++) {
            const int idx = tid + u * 256;
            const int row = idx >> 4, c4 = (idx & 15) * 4;
            *(float4*)(Vs + row * VS_ST + c4) =
                *(const float4*)(vg + (size_t)(j0 + row) * DHn + c4);
        }
        // E window 319x64 -> d-major
        const int l0 = j0 - i0 + 960;
#pragma unroll
        for (int u = 0; u < 20; u++) {
            const int r  = lane + (u % 10) * 32;
            const int c4 = grp * 4 + (u / 10) * 32;
            if (r < WIN) {
                float4 v = *(const float4*)(Eg + (size_t)(l0 + r) * DHn + c4);
                Es[(c4+0)*ES_ST + r] = v.x; Es[(c4+1)*ES_ST + r] = v.y;
                Es[(c4+2)*ES_ST + r] = v.z; Es[(c4+3)*ES_ST + r] = v.w;
            }
        }
        __syncthreads();

        // ---- S = Q.(K+E), 8x8 micro ----
        ull sa[8][4];
#pragma unroll
        for (int i = 0; i < 8; i++)
#pragma unroll
            for (int p = 0; p < 4; p++) sa[i][p] = 0ULL;

#pragma unroll 4
        for (int d = 0; d < 64; d++) {
            float4 q0 = *(const float4*)(Qs + d * QS_ST + ib);
            float4 q1 = *(const float4*)(Qs + d * QS_ST + ib + 4);
            ulonglong2 kA = *(const ulonglong2*)(Ks + d * KS_ST + jb);
            ulonglong2 kB = *(const ulonglong2*)(Ks + d * KS_ST + jb + 4);
            float4 e0 = *(const float4*)(Es + d * ES_ST + wb);
            float4 e1 = *(const float4*)(Es + d * ES_ST + wb + 4);
            float4 e2 = *(const float4*)(Es + d * ES_ST + wb + 8);
            float4 e3 = *(const float4*)(Es + d * ES_ST + wb + 12);
            float e[16] = { e0.x,e0.y,e0.z,e0.w, e1.x,e1.y,e1.z,e1.w,
                            e2.x,e2.y,e2.z,e2.w, e3.x,e3.y,e3.z,e3.w };
            ull pa[8] = { pk2(q0.x,q0.x), pk2(q0.y,q0.y), pk2(q0.z,q0.z), pk2(q0.w,q0.w),
                          pk2(q1.x,q1.x), pk2(q1.y,q1.y), pk2(q1.z,q1.z), pk2(q1.w,q1.w) };
            ull pb[4] = { kA.x, kA.y, kB.x, kB.y };
            ull pr[14];
#pragma unroll
            for (int o = 0; o < 14; o++) pr[o] = pk2(e[o], e[o+1]);
#pragma unroll
            for (int i = 0; i < 8; i++)
#pragma unroll
                for (int p = 0; p < 4; p++) {
                    ull t = add2(pb[p], pr[2*p + 7 - i]);
                    sa[i][p] = fma2(pa[i], t, sa[i][p]);
                }
        }

        // ---- online softmax ----
        float s[8][8];
#pragma unroll
        for (int i = 0; i < 8; i++)
#pragma unroll
            for (int p = 0; p < 4; p++) {
                float2 v = unpk(sa[i][p]);
                s[i][2*p]   = v.x * SCALE;
                s[i][2*p+1] = v.y * SCALE;
            }
#pragma unroll
        for (int i = 0; i < 8; i++) {
            float mx = s[i][0];
#pragma unroll
            for (int j = 1; j < 8; j++) mx = fmaxf(mx, s[i][j]);
#pragma unroll
            for (int o = 16; o; o >>= 1)
                mx = fmaxf(mx, __shfl_xor_sync(0xffffffffu, mx, o));
            const float mn = fmaxf(m_i[i], mx);
            const float al = __expf(m_i[i] - mn);
            m_i[i] = mn;
            float sum = 0.f;
#pragma unroll
            for (int j = 0; j < 8; j++) {
                s[i][j] = __expf(s[i][j] - mn);
                sum += s[i][j];
            }
#pragma unroll
            for (int o = 16; o; o >>= 1)
                sum += __shfl_xor_sync(0xffffffffu, sum, o);
            l_i[i] = l_i[i] * al + sum;
            const ull aa = pk2(al, al);
            o_acc[i][0] = fma2(aa, o_acc[i][0], 0ULL);
            o_acc[i][1] = fma2(aa, o_acc[i][1], 0ULL);
        }

        __syncthreads();   // all Es reads done before Ps overwrite

        // write P, i-major (conflict-free)
#pragma unroll
        for (int i = 0; i < 8; i++) {
            *(float4*)(Ps + (ib+i) * PS_ST + jb)     = make_float4(s[i][0], s[i][1], s[i][2], s[i][3]);
            *(float4*)(Ps + (ib+i) * PS_ST + jb + 4) = make_float4(s[i][4], s[i][5], s[i][6], s[i][7]);
        }
        __syncthreads();

        // ---- O += P @ V (this thread: k-half tk, rows ib..ib+7, cols dq..dq+3) ----
#pragma unroll 4
        for (int k4 = 0; k4 < 128; k4 += 4) {
            const int kk = tk * 128 + k4;
            float4 pv[8];
#pragma unroll
            for (int i = 0; i < 8; i++)
                pv[i] = *(const float4*)(Ps + (ib+i) * PS_ST + kk);
#pragma unroll
            for (int u = 0; u < 4; u++) {
                ulonglong2 vv = *(const ulonglong2*)(Vs + (kk+u) * VS_ST + dq);
#pragma unroll
                for (int i = 0; i < 8; i++) {
                    const float pf = (u == 0) ? pv[i].x : (u == 1) ? pv[i].y
                                   : (u == 2) ? pv[i].z : pv[i].w;
                    const ull pp = pk2(pf, pf);
                    o_acc[i][0] = fma2(pp, vv.x, o_acc[i][0]);
                    o_acc[i][1] = fma2(pp, vv.y, o_acc[i][1]);
                }
            }
        }
    }

    // ---- merge k-halves and epilogue ----
    __syncthreads();
#pragma unroll
    for (int i = 0; i < 8; i++) {
        float2 a = unpk(o_acc[i][0]);
        float2 b = unpk(o_acc[i][1]);
        *(float4*)(Om + ((tk * 64 + ib + i) * 64 + dq)) = make_float4(a.x, a.y, b.x, b.y);
    }
    __syncthreads();

    if (tk == 0) {
        const int bb = bh >> 3, hh = bh & 7;
#pragma unroll
        for (int i = 0; i < 8; i++) {
            const int gi = i0 + ib + i;
            const float f = phase[(size_t)bh * Nn + gi] / l_i[i];
            float4 a = *(const float4*)(Om + ((ib + i) * 64 + dq));
            float4 b = *(const float4*)(Om + ((64 + ib + i) * 64 + dq));
            float4 o;
            o.x = (a.x + b.x) * f; o.y = (a.y + b.y) * f;
            o.z = (a.z + b.z) * f; o.w = (a.w + b.w) * f;
            *(float4*)&g_otmp[(size_t)(bb * Nn + gi) * Dn + hh * 64 + dq] = o;
        }
    }
}

// ---------------------------------------------------------------------------
extern "C" void kernel_launch(void* const* d_in, const int* in_sizes, int n_in,
                              void* d_out, int out_size)
{
    const float* x     = (const float*)d_in[0];
    const float* phase = (const float*)d_in[1];
    const float* E     = (const float*)d_in[2];
    const float* Wq    = (const float*)d_in[3];
    const float* Wk    = (const float*)d_in[4];
    const float* Wv    = (const float*)d_in[5];
    const float* Wo    = (const float*)d_in[6];
    const float* bo    = (const float*)d_in[7];
    float* out = (float*)d_out;

    static const bool s_init = []() {
        cudaFuncSetAttribute(flash_attn, cudaFuncAttributeMaxDynamicSharedMemorySize,
                             SMEM_BYTES);
        return true;
    }();
    (void)s_init;

    dim3 gproj(Dn / 128, (Bn * Nn) / 128);   // (4, 64)

    gemm128<0><<<gproj, 256>>>(x, Wq, nullptr, nullptr);
    gemm128<1><<<gproj, 256>>>(x, Wk, nullptr, nullptr);
    gemm128<2><<<gproj, 256>>>(x, Wv, nullptr, nullptr);

    flash_attn<<<dim3(Nn / 64, BHn), 256, SMEM_BYTES>>>(E, phase);

    gemm128<3><<<gproj, 256>>>(nullptr, Wo, bo, out);
}

// round 7
// speedup vs baseline: 1.8339x; 1.0013x over previous
#include <cuda_runtime.h>

// Problem constants
#define Bn 8
#define Nn 1024
#define Dn 512
#define Hn 8
#define DHn 64
#define BHn (Bn*Hn)          // 64
#define SCALE 0.125f         // 1/sqrt(64)

typedef unsigned long long ull;

__device__ __forceinline__ ull pk2(float lo, float hi) {
    ull r; asm("mov.b64 %0, {%1,%2};" : "=l"(r) : "f"(lo), "f"(hi)); return r;
}
__device__ __forceinline__ ull fma2(ull a, ull b, ull c) {
    ull d; asm("fma.rn.f32x2 %0, %1, %2, %3;" : "=l"(d) : "l"(a), "l"(b), "l"(c)); return d;
}
__device__ __forceinline__ ull add2(ull a, ull b) {
    ull d; asm("add.rn.f32x2 %0, %1, %2;" : "=l"(d) : "l"(a), "l"(b)); return d;
}
__device__ __forceinline__ float2 unpk(ull v) {
    float2 f; asm("mov.b64 {%0,%1}, %2;" : "=f"(f.x), "=f"(f.y) : "l"(v)); return f;
}

// Scratch (allocation-free rule: __device__ globals)
__device__ float g_q[(size_t)BHn*Nn*DHn];            // [bh, n, dh]
__device__ float g_k[(size_t)BHn*Nn*DHn];
__device__ float g_v[(size_t)BHn*Nn*DHn];
__device__ float g_otmp[(size_t)Bn*Nn*Dn];           // concat heads [b, n, h*dh]

// ---------------------------------------------------------------------------
// 128x128-tile NT GEMM, f32x2 packed: C[m,o] = sum_k A[m,k]*W[o,k]
// ---------------------------------------------------------------------------
template<int MODE>
__global__ __launch_bounds__(256) void gemm128(const float* __restrict__ A,
                                               const float* __restrict__ Wm,
                                               const float* __restrict__ bias,
                                               float* __restrict__ Cout)
{
    __shared__ float As[16][136];
    __shared__ float Bs[16][136];
    const int m0 = blockIdx.y * 128;
    const int n0 = blockIdx.x * 128;
    const int tid = threadIdx.x;
    const int tx = tid & 15, ty = tid >> 4;

    const float* Asrc = (MODE == 3) ? (const float*)g_otmp : A;

    ull acc[8][4];
#pragma unroll
    for (int i = 0; i < 8; i++)
#pragma unroll
        for (int p = 0; p < 4; p++) acc[i][p] = 0ULL;

    const int lrow = tid >> 1;          // 0..127
    const int lkk  = (tid & 1) * 8;     // 0,8

    for (int k0 = 0; k0 < Dn; k0 += 16) {
        float4 a0 = *(const float4*)(Asrc + (size_t)(m0 + lrow) * Dn + k0 + lkk);
        float4 a1 = *(const float4*)(Asrc + (size_t)(m0 + lrow) * Dn + k0 + lkk + 4);
        float4 b0 = *(const float4*)(Wm   + (size_t)(n0 + lrow) * Dn + k0 + lkk);
        float4 b1 = *(const float4*)(Wm   + (size_t)(n0 + lrow) * Dn + k0 + lkk + 4);
        As[lkk+0][lrow]=a0.x; As[lkk+1][lrow]=a0.y; As[lkk+2][lrow]=a0.z; As[lkk+3][lrow]=a0.w;
        As[lkk+4][lrow]=a1.x; As[lkk+5][lrow]=a1.y; As[lkk+6][lrow]=a1.z; As[lkk+7][lrow]=a1.w;
        Bs[lkk+0][lrow]=b0.x; Bs[lkk+1][lrow]=b0.y; Bs[lkk+2][lrow]=b0.z; Bs[lkk+3][lrow]=b0.w;
        Bs[lkk+4][lrow]=b1.x; Bs[lkk+5][lrow]=b1.y; Bs[lkk+6][lrow]=b1.z; Bs[lkk+7][lrow]=b1.w;
        __syncthreads();
#pragma unroll
        for (int k = 0; k < 16; k++) {
            float4 av0 = *(const float4*)&As[k][ty*4];
            float4 av1 = *(const float4*)&As[k][64 + ty*4];
            float4 bv0 = *(const float4*)&Bs[k][tx*4];
            float4 bv1 = *(const float4*)&Bs[k][64 + tx*4];
            ull pa[8], pb[4];
            pa[0]=pk2(av0.x,av0.x); pa[1]=pk2(av0.y,av0.y); pa[2]=pk2(av0.z,av0.z); pa[3]=pk2(av0.w,av0.w);
            pa[4]=pk2(av1.x,av1.x); pa[5]=pk2(av1.y,av1.y); pa[6]=pk2(av1.z,av1.z); pa[7]=pk2(av1.w,av1.w);
            pb[0]=pk2(bv0.x,bv0.y); pb[1]=pk2(bv0.z,bv0.w); pb[2]=pk2(bv1.x,bv1.y); pb[3]=pk2(bv1.z,bv1.w);
#pragma unroll
            for (int i = 0; i < 8; i++)
#pragma unroll
                for (int p = 0; p < 4; p++)
                    acc[i][p] = fma2(pa[i], pb[p], acc[i][p]);
        }
        __syncthreads();
    }

#pragma unroll
    for (int i = 0; i < 8; i++) {
        const int m = m0 + ((i < 4) ? (ty*4 + i) : (64 + ty*4 + i - 4));
#pragma unroll
        for (int p = 0; p < 4; p++) {
            const int o = n0 + ((p < 2) ? (tx*4 + p*2) : (64 + tx*4 + (p-2)*2));
            float2 v = unpk(acc[i][p]);
            if (MODE <= 2) {
                float* dst = (MODE == 0) ? g_q : (MODE == 1) ? g_k : g_v;
                const int bb = m >> 10, nn = m & (Nn - 1);
                const int hh = o >> 6,  dd = o & 63;
                *(float2*)&dst[(size_t)(((bb << 3) | hh) << 16) + (nn << 6) + dd] = v;
            } else {
                v.x += bias[o]; v.y += bias[o+1];
                *(float2*)&Cout[(size_t)m * Dn + o] = v;
            }
        }
    }
}

// ---------------------------------------------------------------------------
// Fused flash attention, tile 64i x 256j, 256 threads, micro 8i x 8j.
//   S[i,j] = sum_d Q[d,i] * (K[d,j] + E[d, j-i+63(rel)])   -- combined operand
//   online softmax; O = P @ V (2-way k-split, merged at end); out *= phase/l
// ---------------------------------------------------------------------------
#define JT 256
#define WIN 319
#define QS_ST 68
#define KS_ST 260
#define VS_ST 64
#define ES_ST 320
#define PS_ST 260
#define SM_KS_OFF (64*QS_ST)                 // 4352
#define SM_VS_OFF (SM_KS_OFF + 64*KS_ST)     // 20992
#define SM_EP_OFF (SM_VS_OFF + JT*VS_ST)     // 37376
#define SM_TOT    (SM_EP_OFF + 64*ES_ST)     // 57856 floats
#define SMEM_BYTES (SM_TOT * 4)              // 231424 B

__global__ __launch_bounds__(256, 1) void flash_attn(const float* __restrict__ Eg,
                                                     const float* __restrict__ phase)
{
    extern __shared__ float sm[];
    float* Qs = sm;                    // [64 d][QS_ST]: Qs[d*68 + i]
    float* Ks = sm + SM_KS_OFF;        // [64 d][KS_ST]: Ks[d*260 + j]
    float* Vs = sm + SM_VS_OFF;        // [256 k][64 d]
    float* Es = sm + SM_EP_OFF;        // [64 d][ES_ST]: Es[d*320 + r]
    float* Ps = sm + SM_EP_OFF;        // union: [64 i][PS_ST]
    float* Om = sm + SM_EP_OFF;        // union: [2][64][64] merge buffer

    const int bh = blockIdx.y;
    const int i0 = blockIdx.x * 64;
    const int tid = threadIdx.x;
    const int tx = tid & 31;           // 32 j-groups of 8
    const int ty = tid >> 5;           // 8 i-groups of 8
    const int ib = ty * 8;
    const int jb = tx * 8;
    const int wb = jb - ib + 56;       // E window base, in [0,304], mult of 4
    const int lane = tid & 31;
    const int grp  = tid >> 5;         // c-group for loads (8 groups)
    const int tk = (tid >> 4) & 1;     // AV k-half
    const int dq = (tid & 15) * 4;     // AV d-cols

    const float* qg = g_q + ((size_t)bh * Nn + i0) * DHn;
    const float* kg = g_k + (size_t)bh * Nn * DHn;
    const float* vg = g_v + (size_t)bh * Nn * DHn;

    // ---- load Q tile 64x64 -> d-major (conflict-free: lane == row) ----
#pragma unroll
    for (int u = 0; u < 4; u++) {
        const int r  = lane + (u & 1) * 32;
        const int c4 = grp * 4 + (u >> 1) * 32;
        float4 v = *(const float4*)(qg + r * DHn + c4);
        Qs[(c4+0)*QS_ST + r] = v.x; Qs[(c4+1)*QS_ST + r] = v.y;
        Qs[(c4+2)*QS_ST + r] = v.z; Qs[(c4+3)*QS_ST + r] = v.w;
    }

    ull o_acc[8][2];
    float m_i[8], l_i[8];
#pragma unroll
    for (int i = 0; i < 8; i++) {
        m_i[i] = -1e30f; l_i[i] = 0.f;
        o_acc[i][0] = 0ULL; o_acc[i][1] = 0ULL;
    }

    for (int j0 = 0; j0 < Nn; j0 += JT) {
        __syncthreads();   // prev tile AV done: Ks/Vs/Es(Ps) reusable

        // K tile 256x64 -> d-major
#pragma unroll
        for (int u = 0; u < 16; u++) {
            const int j  = lane + (u & 7) * 32;
            const int c4 = grp * 4 + (u >> 3) * 32;
            float4 v = *(const float4*)(kg + (size_t)(j0 + j) * DHn + c4);
            Ks[(c4+0)*KS_ST + j] = v.x; Ks[(c4+1)*KS_ST + j] = v.y;
            Ks[(c4+2)*KS_ST + j] = v.z; Ks[(c4+3)*KS_ST + j] = v.w;
        }
        // V tile 256x64 natural (coalesced)
#pragma unroll
        for (int u = 0; u < 16; u++) {
            const int idx = tid + u * 256;
            const int row = idx >> 4, c4 = (idx & 15) * 4;
            *(float4*)(Vs + row * VS_ST + c4) =
                *(const float4*)(vg + (size_t)(j0 + row) * DHn + c4);
        }
        // E window 319x64 -> d-major
        const int l0 = j0 - i0 + 960;
#pragma unroll
        for (int u = 0; u < 20; u++) {
            const int r  = lane + (u % 10) * 32;
            const int c4 = grp * 4 + (u / 10) * 32;
            if (r < WIN) {
                float4 v = *(const float4*)(Eg + (size_t)(l0 + r) * DHn + c4);
                Es[(c4+0)*ES_ST + r] = v.x; Es[(c4+1)*ES_ST + r] = v.y;
                Es[(c4+2)*ES_ST + r] = v.z; Es[(c4+3)*ES_ST + r] = v.w;
            }
        }
        __syncthreads();

        // ---- S = Q.(K+E), 8x8 micro ----
        ull sa[8][4];
#pragma unroll
        for (int i = 0; i < 8; i++)
#pragma unroll
            for (int p = 0; p < 4; p++) sa[i][p] = 0ULL;

#pragma unroll 4
        for (int d = 0; d < 64; d++) {
            float4 q0 = *(const float4*)(Qs + d * QS_ST + ib);
            float4 q1 = *(const float4*)(Qs + d * QS_ST + ib + 4);
            ulonglong2 kA = *(const ulonglong2*)(Ks + d * KS_ST + jb);
            ulonglong2 kB = *(const ulonglong2*)(Ks + d * KS_ST + jb + 4);
            float4 e0 = *(const float4*)(Es + d * ES_ST + wb);
            float4 e1 = *(const float4*)(Es + d * ES_ST + wb + 4);
            float4 e2 = *(const float4*)(Es + d * ES_ST + wb + 8);
            float4 e3 = *(const float4*)(Es + d * ES_ST + wb + 12);
            float e[16] = { e0.x,e0.y,e0.z,e0.w, e1.x,e1.y,e1.z,e1.w,
                            e2.x,e2.y,e2.z,e2.w, e3.x,e3.y,e3.z,e3.w };
            ull pa[8] = { pk2(q0.x,q0.x), pk2(q0.y,q0.y), pk2(q0.z,q0.z), pk2(q0.w,q0.w),
                          pk2(q1.x,q1.x), pk2(q1.y,q1.y), pk2(q1.z,q1.z), pk2(q1.w,q1.w) };
            ull pb[4] = { kA.x, kA.y, kB.x, kB.y };
            ull pr[14];
#pragma unroll
            for (int o = 0; o < 14; o++) pr[o] = pk2(e[o], e[o+1]);
#pragma unroll
            for (int i = 0; i < 8; i++)
#pragma unroll
                for (int p = 0; p < 4; p++) {
                    ull t = add2(pb[p], pr[2*p + 7 - i]);
                    sa[i][p] = fma2(pa[i], t, sa[i][p]);
                }
        }

        // ---- online softmax ----
        float s[8][8];
#pragma unroll
        for (int i = 0; i < 8; i++)
#pragma unroll
            for (int p = 0; p < 4; p++) {
                float2 v = unpk(sa[i][p]);
                s[i][2*p]   = v.x * SCALE;
                s[i][2*p+1] = v.y * SCALE;
            }
#pragma unroll
        for (int i = 0; i < 8; i++) {
            float mx = s[i][0];
#pragma unroll
            for (int j = 1; j < 8; j++) mx = fmaxf(mx, s[i][j]);
#pragma unroll
            for (int o = 16; o; o >>= 1)
                mx = fmaxf(mx, __shfl_xor_sync(0xffffffffu, mx, o));
            const float mn = fmaxf(m_i[i], mx);
            const float al = __expf(m_i[i] - mn);
            m_i[i] = mn;
            float sum = 0.f;
#pragma unroll
            for (int j = 0; j < 8; j++) {
                s[i][j] = __expf(s[i][j] - mn);
                sum += s[i][j];
            }
#pragma unroll
            for (int o = 16; o; o >>= 1)
                sum += __shfl_xor_sync(0xffffffffu, sum, o);
            l_i[i] = l_i[i] * al + sum;
            const ull aa = pk2(al, al);
            o_acc[i][0] = fma2(aa, o_acc[i][0], 0ULL);
            o_acc[i][1] = fma2(aa, o_acc[i][1], 0ULL);
        }

        __syncthreads();   // all Es reads done before Ps overwrite

        // write P, i-major (conflict-free)
#pragma unroll
        for (int i = 0; i < 8; i++) {
            *(float4*)(Ps + (ib+i) * PS_ST + jb)     = make_float4(s[i][0], s[i][1], s[i][2], s[i][3]);
            *(float4*)(Ps + (ib+i) * PS_ST + jb + 4) = make_float4(s[i][4], s[i][5], s[i][6], s[i][7]);
        }
        __syncthreads();

        // ---- O += P @ V (this thread: k-half tk, rows ib..ib+7, cols dq..dq+3) ----
#pragma unroll 4
        for (int k4 = 0; k4 < 128; k4 += 4) {
            const int kk = tk * 128 + k4;
            float4 pv[8];
#pragma unroll
            for (int i = 0; i < 8; i++)
                pv[i] = *(const float4*)(Ps + (ib+i) * PS_ST + kk);
#pragma unroll
            for (int u = 0; u < 4; u++) {
                ulonglong2 vv = *(const ulonglong2*)(Vs + (kk+u) * VS_ST + dq);
#pragma unroll
                for (int i = 0; i < 8; i++) {
                    const float pf = (u == 0) ? pv[i].x : (u == 1) ? pv[i].y
                                   : (u == 2) ? pv[i].z : pv[i].w;
                    const ull pp = pk2(pf, pf);
                    o_acc[i][0] = fma2(pp, vv.x, o_acc[i][0]);
                    o_acc[i][1] = fma2(pp, vv.y, o_acc[i][1]);
                }
            }
        }
    }

    // ---- merge k-halves and epilogue ----
    __syncthreads();
#pragma unroll
    for (int i = 0; i < 8; i++) {
        float2 a = unpk(o_acc[i][0]);
        float2 b = unpk(o_acc[i][1]);
        *(float4*)(Om + ((tk * 64 + ib + i) * 64 + dq)) = make_float4(a.x, a.y, b.x, b.y);
    }
    __syncthreads();

    if (tk == 0) {
        const int bb = bh >> 3, hh = bh & 7;
#pragma unroll
        for (int i = 0; i < 8; i++) {
            const int gi = i0 + ib + i;
            const float f = phase[(size_t)bh * Nn + gi] / l_i[i];
            float4 a = *(const float4*)(Om + ((ib + i) * 64 + dq));
            float4 b = *(const float4*)(Om + ((64 + ib + i) * 64 + dq));
            float4 o;
            o.x = (a.x + b.x) * f; o.y = (a.y + b.y) * f;
            o.z = (a.z + b.z) * f; o.w = (a.w + b.w) * f;
            *(float4*)&g_otmp[(size_t)(bb * Nn + gi) * Dn + hh * 64 + dq] = o;
        }
    }
}

// ---------------------------------------------------------------------------
extern "C" void kernel_launch(void* const* d_in, const int* in_sizes, int n_in,
                              void* d_out, int out_size)
{
    const float* x     = (const float*)d_in[0];
    const float* phase = (const float*)d_in[1];
    const float* E     = (const float*)d_in[2];
    const float* Wq    = (const float*)d_in[3];
    const float* Wk    = (const float*)d_in[4];
    const float* Wv    = (const float*)d_in[5];
    const float* Wo    = (const float*)d_in[6];
    const float* bo    = (const float*)d_in[7];
    float* out = (float*)d_out;

    static const bool s_init = []() {
        cudaFuncSetAttribute(flash_attn, cudaFuncAttributeMaxDynamicSharedMemorySize,
                             SMEM_BYTES);
        return true;
    }();
    (void)s_init;

    dim3 gproj(Dn / 128, (Bn * Nn) / 128);   // (4, 64)

    gemm128<0><<<gproj, 256>>>(x, Wq, nullptr, nullptr);
    gemm128<1><<<gproj, 256>>>(x, Wk, nullptr, nullptr);
    gemm128<2><<<gproj, 256>>>(x, Wv, nullptr, nullptr);

    flash_attn<<<dim3(Nn / 64, BHn), 256, SMEM_BYTES>>>(E, phase);

    gemm128<3><<<gproj, 256>>>(nullptr, Wo, bo, out);
}